// round 15
// baseline (speedup 1.0000x reference)
#include <cuda_runtime.h>
#include <cuda_fp16.h>
#include <math.h>

#define D       20
#define K1      30
#define DP      32          // table row stride (128B)
#define NRELP1  201
#define NTIME   365
#define NLAYERS 3
#define MAXN    1000000
#define NHW     64          // uints per node row in g_NH (256B)

// ---------------- scratch (device globals; no runtime allocation) ----------------
__device__ __align__(16) float    g_buf0[MAXN * D];               // 80 MB
__device__ __align__(16) float    g_buf1[MAXN * D];               // 80 MB
__device__ __align__(16) float    g_PbP[NRELP1 * DP];
__device__ __align__(16) float    g_PcP[NRELP1 * DP];
__device__ __align__(16) float    g_PBC[NRELP1 * NRELP1 * DP];    // Pb[r]+Pc[q], 5.2 MB
__device__ __align__(16) float    g_RWp[3 * NRELP1 * DP];
__device__ __align__(16) float    g_TWp[3 * NTIME * DP];
__device__ __align__(16) float    g_RT[(size_t)3 * NRELP1 * NTIME * DP];  // RW+TW, 28.2 MB
__device__ __align__(16) float    g_S0[NRELP1 * NRELP1];
// packed fp16 node row: HA uints 0..14 (pad 15), HT2 uints 16..25,
// HT0 uints 32..41, HT1 uints 42..51; pads never read.
__device__ __align__(16) unsigned g_NH[(size_t)MAXN * NHW];       // 256 MB

// vectorized global float4 reduction (sm_90+) — R7 champion exact
__device__ __forceinline__ void red_add_v4(float* addr, float a, float b, float c, float d) {
    asm volatile(
        "{ .reg .u64 p; cvta.to.global.u64 p, %0;\n\t"
        "  red.global.add.v4.f32 [p], {%1, %2, %3, %4}; }\n\t"
        :: "l"(addr), "f"(a), "f"(b), "f"(c), "f"(d) : "memory");
}

__device__ __forceinline__ float leaky(float x) { return x > 0.f ? x : 0.01f * x; }

// ---------------- small-table precompute ----------------
__global__ void k_tables(const float* __restrict__ rela, const float* __restrict__ tem,
                         const float* __restrict__ w1,
                         const float* __restrict__ wp, const float* __restrict__ wn,
                         const float* __restrict__ wf)
{
    int i = blockIdx.x * blockDim.x + threadIdx.x;
    const int NPB  = NRELP1 * DP;
    const int NRW  = 3 * NRELP1 * DP;
    const int NTW  = 3 * NTIME * DP;
    if (i < NPB) {
        int r = i / DP, k = i % DP;
        float a = 0.f;
        if (k < K1) {
            #pragma unroll
            for (int j = 0; j < D; j++) a = fmaf(rela[r * D + j], w1[k * (3 * D) + D + j], a);
        }
        g_PbP[i] = a;
    } else if (i < 2 * NPB) {
        int t = i - NPB;
        int r = t / DP, k = t % DP;
        float a = 0.f;
        if (k < K1) {
            #pragma unroll
            for (int j = 0; j < D; j++) a = fmaf(rela[r * D + j], w1[k * (3 * D) + 2 * D + j], a);
        }
        g_PcP[t] = a;
    } else if (i < 2 * NPB + NRW) {
        int t = i - 2 * NPB;
        int s = t / (NRELP1 * DP);
        int rem = t % (NRELP1 * DP);
        int r = rem / DP, o = rem % DP;
        float a = 0.f;
        if (o < D) {
            const float* W = (s == 0) ? wp : ((s == 1) ? wn : wf);
            #pragma unroll
            for (int j = 0; j < D; j++) a = fmaf(rela[r * D + j], W[o * D + j], a);
        }
        g_RWp[t] = a;
    } else if (i < 2 * NPB + NRW + NTW) {
        int t = i - 2 * NPB - NRW;
        int s = t / (NTIME * DP);
        int rem = t % (NTIME * DP);
        int tt = rem / DP, o = rem % DP;
        float a = 0.f;
        if (o < D) {
            const float* W = (s == 0) ? wp : ((s == 1) ? wn : wf);
            #pragma unroll
            for (int j = 0; j < D; j++) a = fmaf(tem[tt * D + j], W[o * D + j], a);
        }
        g_TWp[t] = a;
    }
}

// PBC[r][q][k] = PbP[r][k] + PcP[q][k]
__global__ void k_pbc()
{
    int i = blockIdx.x * blockDim.x + threadIdx.x;
    if (i >= NRELP1 * NRELP1 * DP) return;
    int k = i & (DP - 1);
    int rq = i >> 5;
    int q = rq % NRELP1, r = rq / NRELP1;
    g_PBC[i] = g_PbP[r * DP + k] + g_PcP[q * DP + k];
}

// RT[sel][r][ta][k] = RWp[sel][r][k] + TWp[sel][ta][k]  (one gather instead of two)
__global__ void k_rt()
{
    long long i = (long long)blockIdx.x * blockDim.x + threadIdx.x;
    if (i >= (long long)3 * NRELP1 * NTIME * DP) return;
    int k = (int)(i & (DP - 1));
    long long rem = i >> 5;
    int ta = (int)(rem % NTIME);
    long long rr = rem / NTIME;
    int r = (int)(rr % NRELP1);
    int sel = (int)(rr / NRELP1);
    g_RT[i] = g_RWp[(sel * NRELP1 + r) * DP + k] + g_TWp[(sel * NTIME + ta) * DP + k];
}

// layer-0 score table
__global__ void k_s0(const float* __restrict__ w2)
{
    int i = blockIdx.x * blockDim.x + threadIdx.x;
    if (i >= NRELP1 * NRELP1) return;
    int r = i / NRELP1, q = i % NRELP1;
    float s = 0.f;
    #pragma unroll
    for (int k = 0; k < K1; k++) {
        float a = g_PbP[r * DP + k] + g_PcP[q * DP + k];
        a = fmaxf(a, 0.f);
        s = fmaf(a, w2[k], s);
    }
    g_S0[i] = 1.f / (1.f + __expf(-s));
}

// ---------------- node precompute (half2 math): packed fp16 row HA + HT0/1/2 --------
__global__ __launch_bounds__(256) void k_node(
    const float* __restrict__ hin,
    const float* __restrict__ w1, const float* __restrict__ wp,
    const float* __restrict__ wn, const float* __restrict__ wf, int Nn)
{
    extern __shared__ float sm[];
    unsigned* s_w1a2 = (unsigned*)sm;                 // [K1*10]  w1a rows, half2-packed
    unsigned* s_W2   = (unsigned*)sm + 300;           // [3*D*10] W rows, half2-packed
    float*    s_h    = sm + 900;                      // [256*21] staging
    unsigned* s_row  = (unsigned*)(sm + 900 + 256 * 21);   // [256*65]

    int tid = threadIdx.x;
    for (int i = tid; i < K1 * 10; i += 256) {
        int o = i / 10, jj = i % 10;
        __half2 hh = __floats2half2_rn(w1[o * (3 * D) + 2 * jj], w1[o * (3 * D) + 2 * jj + 1]);
        s_w1a2[i] = *(unsigned*)&hh;
    }
    for (int i = tid; i < 3 * D * 10; i += 256) {
        int s = i / (D * 10); int rm = i % (D * 10);
        int o = rm / 10, jj = rm % 10;
        const float* W = (s == 0) ? wp : ((s == 1) ? wn : wf);
        __half2 hh = __floats2half2_rn(W[o * D + 2 * jj], W[o * D + 2 * jj + 1]);
        s_W2[i] = *(unsigned*)&hh;
    }
    int base = blockIdx.x * 256;
    int nblk = Nn - base; if (nblk > 256) nblk = 256;

    // stage hidden rows coalesced, fuse leaky
    for (int f = tid; f < nblk * D; f += 256) {
        float v = hin[(size_t)base * D + f];
        s_h[(f / D) * 21 + (f % D)] = leaky(v);
    }
    __syncthreads();

    __half2 h2[10];
    #pragma unroll
    for (int jj = 0; jj < 10; jj++)
        h2[jj] = __floats2half2_rn(s_h[tid * 21 + 2 * jj], s_h[tid * 21 + 2 * jj + 1]);

    unsigned* row = s_row + tid * 65;
    #pragma unroll
    for (int op = 0; op < K1 / 2; op++) {
        __half2 accA = __floats2half2_rn(0.f, 0.f);
        __half2 accB = __floats2half2_rn(0.f, 0.f);
        #pragma unroll
        for (int jj = 0; jj < 10; jj++) {
            accA = __hfma2(h2[jj], *(const __half2*)&s_w1a2[(2 * op) * 10 + jj], accA);
            accB = __hfma2(h2[jj], *(const __half2*)&s_w1a2[(2 * op + 1) * 10 + jj], accB);
        }
        float2 fa = __half22float2(accA);
        float2 fb = __half22float2(accB);
        __half2 hh = __floats2half2_rn(fa.x + fa.y, fb.x + fb.y);
        row[op] = *(unsigned*)&hh;
    }
    row[15] = 0u;
    #pragma unroll
    for (int sel = 0; sel < 3; sel++) {
        int uo = (sel == 2) ? 16 : (32 + 10 * sel);
        #pragma unroll
        for (int op = 0; op < D / 2; op++) {
            __half2 accA = __floats2half2_rn(0.f, 0.f);
            __half2 accB = __floats2half2_rn(0.f, 0.f);
            #pragma unroll
            for (int jj = 0; jj < 10; jj++) {
                accA = __hfma2(h2[jj], *(const __half2*)&s_W2[sel * 200 + (2 * op) * 10 + jj], accA);
                accB = __hfma2(h2[jj], *(const __half2*)&s_W2[sel * 200 + (2 * op + 1) * 10 + jj], accB);
            }
            float2 fa = __half22float2(accA);
            float2 fb = __half22float2(accB);
            __half2 hh = __floats2half2_rn(fa.x + fa.y, fb.x + fb.y);
            row[uo + op] = *(unsigned*)&hh;
        }
    }
    __syncthreads();

    // coalesced store, skipping never-read pad uints (26..31, 52..63)
    for (int f = tid; f < nblk * NHW; f += 256) {
        int nn = f >> 6, u = f & 63;
        if (u < 26 || (u >= 32 && u < 52))
            g_NH[(size_t)(base + nn) * NHW + u] = s_row[nn * 65 + u];
    }
}

// ---------------- layer 0: h == 0, 8 lanes per edge, single RT gather ---------------
__global__ __launch_bounds__(256) void k_edge0(
    const int* __restrict__ rel, const int* __restrict__ qrel,
    const int* __restrict__ rtime, const int* __restrict__ dst,
    float* __restrict__ hout, int E)
{
    int tid = threadIdx.x, lane = tid & 31, wid = tid >> 5;
    int grp = lane >> 3, sub = lane & 7;
    int base = (blockIdx.x * 8 + wid) * 32;
    #pragma unroll
    for (int it = 0; it < 8; it++) {
        int ew = base + it * 4 + grp;
        bool valid = ew < E;
        int ei = valid ? ew : 0;
        int dn = dst[ei], r = rel[ei], q = qrel[ei], rt = rtime[ei];
        int sel = (rt > 0) ? 2 : ((rt == 0) ? 1 : 0);
        int ta = rt < 0 ? -rt : rt;
        float score = g_S0[r * NRELP1 + q];
        if (valid && sub < 5) {
            float4 rt4 = *(const float4*)(g_RT +
                ((size_t)(sel * NRELP1 + r) * NTIME + ta) * DP + sub * 4);
            red_add_v4(hout + (size_t)dn * D + sub * 4,
                       score * rt4.x, score * rt4.y, score * rt4.z, score * rt4.w);
        }
    }
}

// ---------------- generic layer: 8 lanes/edge, fp16 node row, single RT gather ------
__global__ __launch_bounds__(256) void k_edge(
    const int* __restrict__ src, const int* __restrict__ dst,
    const int* __restrict__ rel, const int* __restrict__ qrel,
    const int* __restrict__ rtime, const float* __restrict__ w2,
    float* __restrict__ hout, int E)
{
    int tid = threadIdx.x, lane = tid & 31, wid = tid >> 5;
    int grp = lane >> 3, sub = lane & 7;
    float w2r0 = (sub * 4 + 0 < K1) ? w2[sub * 4 + 0] : 0.f;
    float w2r1 = (sub * 4 + 1 < K1) ? w2[sub * 4 + 1] : 0.f;
    float w2r2 = (sub * 4 + 2 < K1) ? w2[sub * 4 + 2] : 0.f;
    float w2r3 = (sub * 4 + 3 < K1) ? w2[sub * 4 + 3] : 0.f;
    int base = (blockIdx.x * 8 + wid) * 32;
    #pragma unroll
    for (int it = 0; it < 8; it++) {
        int ew = base + it * 4 + grp;
        bool valid = ew < E;
        int ei = valid ? ew : 0;
        int sn = src[ei], dn = dst[ei], r = rel[ei], q = qrel[ei], rt = rtime[ei];
        int sel = (rt > 0) ? 2 : ((rt == 0) ? 1 : 0);
        int ta = rt < 0 ? -rt : rt;
        const unsigned* nrow = g_NH + (size_t)sn * NHW;
        // attention: 8 lanes cover 32 halves of HA
        uint2 hv = *(const uint2*)(nrow + sub * 2);
        float2 f01 = __half22float2(*(const __half2*)&hv.x);
        float2 f23 = __half22float2(*(const __half2*)&hv.y);
        float4 pb = *(const float4*)(g_PBC + (size_t)(r * NRELP1 + q) * DP + sub * 4);
        float p = fmaxf(f01.x + pb.x, 0.f) * w2r0;
        p = fmaf(fmaxf(f01.y + pb.y, 0.f), w2r1, p);
        p = fmaf(fmaxf(f23.x + pb.z, 0.f), w2r2, p);
        p = fmaf(fmaxf(f23.y + pb.w, 0.f), w2r3, p);
        p += __shfl_xor_sync(0xffffffffu, p, 1);
        p += __shfl_xor_sync(0xffffffffu, p, 2);
        p += __shfl_xor_sync(0xffffffffu, p, 4);
        float score = 1.f / (1.f + __expf(-p));
        // message: lanes 0..4 cover 20 floats
        if (valid && sub < 5) {
            int uo = (sel == 2) ? 16 : (32 + 10 * sel);
            uint2 tv = *(const uint2*)(nrow + uo + sub * 2);
            float2 t01 = __half22float2(*(const __half2*)&tv.x);
            float2 t23 = __half22float2(*(const __half2*)&tv.y);
            float4 rt4 = *(const float4*)(g_RT +
                ((size_t)(sel * NRELP1 + r) * NTIME + ta) * DP + sub * 4);
            red_add_v4(hout + (size_t)dn * D + sub * 4,
                       score * (t01.x + rt4.x), score * (t01.y + rt4.y),
                       score * (t23.x + rt4.z), score * (t23.y + rt4.w));
        }
    }
}

// ---------------- final: leaky -> dot(w_cls) + b -> scatter ----------------
__global__ __launch_bounds__(256) void k_final(
    const float* __restrict__ hin, const int* __restrict__ nb,
    const int* __restrict__ ne, const float* __restrict__ wcls,
    const float* __restrict__ bcls, const int* __restrict__ pne,
    float* __restrict__ out, int n)
{
    int i = blockIdx.x * blockDim.x + threadIdx.x;
    if (i >= n) return;
    const float4* hp = (const float4*)(hin + (size_t)i * D);
    float acc = bcls[0];
    #pragma unroll
    for (int g = 0; g < D / 4; g++) {
        float4 v = hp[g];
        acc = fmaf(leaky(v.x), __ldg(wcls + 4 * g + 0), acc);
        acc = fmaf(leaky(v.y), __ldg(wcls + 4 * g + 1), acc);
        acc = fmaf(leaky(v.z), __ldg(wcls + 4 * g + 2), acc);
        acc = fmaf(leaky(v.w), __ldg(wcls + 4 * g + 3), acc);
    }
    long long idx = (long long)nb[i] * (long long)pne[0] + (long long)ne[i];
    out[idx] = acc;
}

// ---------------- host ----------------
extern "C" void kernel_launch(void* const* d_in, const int* in_sizes, int n_in,
                              void* d_out, int out_size)
{
    const int*   src   = (const int*)d_in[0];
    const int*   dst   = (const int*)d_in[1];
    const int*   rel   = (const int*)d_in[2];
    const int*   qrel  = (const int*)d_in[3];
    const int*   rtime = (const int*)d_in[4];
    const int*   nb    = (const int*)d_in[5];
    const int*   ne    = (const int*)d_in[6];
    const float* rela  = (const float*)d_in[7];
    const float* tem   = (const float*)d_in[8];
    const float* w1    = (const float*)d_in[9];
    const float* w2    = (const float*)d_in[10];
    const float* wp    = (const float*)d_in[11];
    const float* wn    = (const float*)d_in[12];
    const float* wf    = (const float*)d_in[13];
    const float* wcls  = (const float*)d_in[14];
    const float* bcls  = (const float*)d_in[15];
    const int*   pne   = (const int*)d_in[17];

    int E  = in_sizes[0] / NLAYERS;
    int Nn = in_sizes[5];

    float *b0, *b1;
    cudaGetSymbolAddress((void**)&b0, g_buf0);
    cudaGetSymbolAddress((void**)&b1, g_buf1);
    size_t bufBytes = (size_t)Nn * D * sizeof(float);

    const int SMEM_NODE = 900 * 4 + 256 * 21 * 4 + 256 * 65 * 4;  // ~92 KB
    static int smem_set = 0;
    if (!smem_set) {
        cudaFuncSetAttribute(k_node, cudaFuncAttributeMaxDynamicSharedMemorySize, SMEM_NODE);
        smem_set = 1;
    }

    // small tables, then fused RT table
    const int NTAB = 2 * NRELP1 * DP + 3 * NRELP1 * DP + 3 * NTIME * DP;
    k_tables<<<(NTAB + 255) / 256, 256>>>(rela, tem, w1, wp, wn, wf);
    k_s0<<<(NRELP1 * NRELP1 + 255) / 256, 256>>>(w2);
    k_pbc<<<(NRELP1 * NRELP1 * DP + 255) / 256, 256>>>();
    long long nrt = (long long)3 * NRELP1 * NTIME * DP;
    k_rt<<<(int)((nrt + 255) / 256), 256>>>();

    int gE = (E + 255) / 256;        // 256 edges per block (8 warps x 32 edges)
    int gN = (Nn + 255) / 256;

    // layer 0 (h = 0): accumulate into buf1
    cudaMemsetAsync(b1, 0, bufBytes);
    k_edge0<<<gE, 256>>>(rel, qrel, rtime, dst, b1, E);

    // layer 1: node precompute from buf1, edges -> buf0
    k_node<<<gN, 256, SMEM_NODE>>>(b1, w1, wp, wn, wf, Nn);
    cudaMemsetAsync(b0, 0, bufBytes);
    k_edge<<<gE, 256>>>(src + E, dst + E, rel + E, qrel + E, rtime + E, w2, b0, E);

    // layer 2: node precompute from buf0, edges -> buf1
    k_node<<<gN, 256, SMEM_NODE>>>(b0, w1, wp, wn, wf, Nn);
    cudaMemsetAsync(b1, 0, bufBytes);
    k_edge<<<gE, 256>>>(src + 2 * E, dst + 2 * E, rel + 2 * E, qrel + 2 * E, rtime + 2 * E,
                        w2, b1, E);

    // output: zero then scatter
    cudaMemsetAsync(d_out, 0, (size_t)out_size * sizeof(float));
    k_final<<<(Nn + 255) / 256, 256>>>(b1, nb, ne, wcls, bcls, pne, (float*)d_out, Nn);
}

// round 16
// speedup vs baseline: 1.0548x; 1.0548x over previous
#include <cuda_runtime.h>
#include <cuda_fp16.h>
#include <math.h>

#define D       20
#define K1      30
#define DP      32          // table row stride (128B)
#define NRELP1  201
#define NTIME   365
#define NLAYERS 3
#define MAXN    1000000
#define NHW     64          // uints per node row in g_NH (256B)
#define EPW     64          // edges per warp (16 iterations x 4 edges)

// ---------------- scratch (device globals; no runtime allocation) ----------------
__device__ __align__(16) float    g_buf0[MAXN * D];               // 80 MB
__device__ __align__(16) float    g_buf1[MAXN * D];               // 80 MB
__device__ __align__(16) float    g_PbP[NRELP1 * DP];
__device__ __align__(16) float    g_PcP[NRELP1 * DP];
__device__ __align__(16) float    g_PBC[NRELP1 * NRELP1 * DP];    // Pb[r]+Pc[q], 5.2 MB
__device__ __align__(16) float    g_RWp[3 * NRELP1 * DP];
__device__ __align__(16) float    g_TWp[3 * NTIME * DP];
__device__ __align__(16) float    g_S0[NRELP1 * NRELP1];
// packed fp16 node row: HA uints 0..14 (pad 15), HT2 uints 16..25,
// HT0 uints 32..41, HT1 uints 42..51; pads never read.
__device__ __align__(16) unsigned g_NH[(size_t)MAXN * NHW];       // 256 MB

// vectorized global float4 reduction (sm_90+) — R7 champion exact
__device__ __forceinline__ void red_add_v4(float* addr, float a, float b, float c, float d) {
    asm volatile(
        "{ .reg .u64 p; cvta.to.global.u64 p, %0;\n\t"
        "  red.global.add.v4.f32 [p], {%1, %2, %3, %4}; }\n\t"
        :: "l"(addr), "f"(a), "f"(b), "f"(c), "f"(d) : "memory");
}

__device__ __forceinline__ float leaky(float x) { return x > 0.f ? x : 0.01f * x; }

// ---------------- small-table precompute ----------------
__global__ void k_tables(const float* __restrict__ rela, const float* __restrict__ tem,
                         const float* __restrict__ w1,
                         const float* __restrict__ wp, const float* __restrict__ wn,
                         const float* __restrict__ wf)
{
    int i = blockIdx.x * blockDim.x + threadIdx.x;
    const int NPB  = NRELP1 * DP;
    const int NRW  = 3 * NRELP1 * DP;
    const int NTW  = 3 * NTIME * DP;
    if (i < NPB) {
        int r = i / DP, k = i % DP;
        float a = 0.f;
        if (k < K1) {
            #pragma unroll
            for (int j = 0; j < D; j++) a = fmaf(rela[r * D + j], w1[k * (3 * D) + D + j], a);
        }
        g_PbP[i] = a;
    } else if (i < 2 * NPB) {
        int t = i - NPB;
        int r = t / DP, k = t % DP;
        float a = 0.f;
        if (k < K1) {
            #pragma unroll
            for (int j = 0; j < D; j++) a = fmaf(rela[r * D + j], w1[k * (3 * D) + 2 * D + j], a);
        }
        g_PcP[t] = a;
    } else if (i < 2 * NPB + NRW) {
        int t = i - 2 * NPB;
        int s = t / (NRELP1 * DP);
        int rem = t % (NRELP1 * DP);
        int r = rem / DP, o = rem % DP;
        float a = 0.f;
        if (o < D) {
            const float* W = (s == 0) ? wp : ((s == 1) ? wn : wf);
            #pragma unroll
            for (int j = 0; j < D; j++) a = fmaf(rela[r * D + j], W[o * D + j], a);
        }
        g_RWp[t] = a;
    } else if (i < 2 * NPB + NRW + NTW) {
        int t = i - 2 * NPB - NRW;
        int s = t / (NTIME * DP);
        int rem = t % (NTIME * DP);
        int tt = rem / DP, o = rem % DP;
        float a = 0.f;
        if (o < D) {
            const float* W = (s == 0) ? wp : ((s == 1) ? wn : wf);
            #pragma unroll
            for (int j = 0; j < D; j++) a = fmaf(tem[tt * D + j], W[o * D + j], a);
        }
        g_TWp[t] = a;
    }
}

// PBC[r][q][k] = PbP[r][k] + PcP[q][k]
__global__ void k_pbc()
{
    int i = blockIdx.x * blockDim.x + threadIdx.x;
    if (i >= NRELP1 * NRELP1 * DP) return;
    int k = i & (DP - 1);
    int rq = i >> 5;
    int q = rq % NRELP1, r = rq / NRELP1;
    g_PBC[i] = g_PbP[r * DP + k] + g_PcP[q * DP + k];
}

// layer-0 score table
__global__ void k_s0(const float* __restrict__ w2)
{
    int i = blockIdx.x * blockDim.x + threadIdx.x;
    if (i >= NRELP1 * NRELP1) return;
    int r = i / NRELP1, q = i % NRELP1;
    float s = 0.f;
    #pragma unroll
    for (int k = 0; k < K1; k++) {
        float a = g_PbP[r * DP + k] + g_PcP[q * DP + k];
        a = fmaxf(a, 0.f);
        s = fmaf(a, w2[k], s);
    }
    g_S0[i] = 1.f / (1.f + __expf(-s));
}

// ---------------- node precompute (half2 math): packed fp16 row HA + HT0/1/2 --------
__global__ __launch_bounds__(256) void k_node(
    const float* __restrict__ hin,
    const float* __restrict__ w1, const float* __restrict__ wp,
    const float* __restrict__ wn, const float* __restrict__ wf, int Nn)
{
    extern __shared__ float sm[];
    unsigned* s_w1a2 = (unsigned*)sm;                 // [K1*10]  w1a rows, half2-packed
    unsigned* s_W2   = (unsigned*)sm + 300;           // [3*D*10] W rows, half2-packed
    float*    s_h    = sm + 900;                      // [256*21] staging
    unsigned* s_row  = (unsigned*)(sm + 900 + 256 * 21);   // [256*65]

    int tid = threadIdx.x;
    for (int i = tid; i < K1 * 10; i += 256) {
        int o = i / 10, jj = i % 10;
        __half2 hh = __floats2half2_rn(w1[o * (3 * D) + 2 * jj], w1[o * (3 * D) + 2 * jj + 1]);
        s_w1a2[i] = *(unsigned*)&hh;
    }
    for (int i = tid; i < 3 * D * 10; i += 256) {
        int s = i / (D * 10); int rm = i % (D * 10);
        int o = rm / 10, jj = rm % 10;
        const float* W = (s == 0) ? wp : ((s == 1) ? wn : wf);
        __half2 hh = __floats2half2_rn(W[o * D + 2 * jj], W[o * D + 2 * jj + 1]);
        s_W2[i] = *(unsigned*)&hh;
    }
    int base = blockIdx.x * 256;
    int nblk = Nn - base; if (nblk > 256) nblk = 256;

    // stage hidden rows coalesced, fuse leaky
    for (int f = tid; f < nblk * D; f += 256) {
        float v = hin[(size_t)base * D + f];
        s_h[(f / D) * 21 + (f % D)] = leaky(v);
    }
    __syncthreads();

    __half2 h2[10];
    #pragma unroll
    for (int jj = 0; jj < 10; jj++)
        h2[jj] = __floats2half2_rn(s_h[tid * 21 + 2 * jj], s_h[tid * 21 + 2 * jj + 1]);

    unsigned* row = s_row + tid * 65;
    #pragma unroll
    for (int op = 0; op < K1 / 2; op++) {
        __half2 accA = __floats2half2_rn(0.f, 0.f);
        __half2 accB = __floats2half2_rn(0.f, 0.f);
        #pragma unroll
        for (int jj = 0; jj < 10; jj++) {
            accA = __hfma2(h2[jj], *(const __half2*)&s_w1a2[(2 * op) * 10 + jj], accA);
            accB = __hfma2(h2[jj], *(const __half2*)&s_w1a2[(2 * op + 1) * 10 + jj], accB);
        }
        float2 fa = __half22float2(accA);
        float2 fb = __half22float2(accB);
        __half2 hh = __floats2half2_rn(fa.x + fa.y, fb.x + fb.y);
        row[op] = *(unsigned*)&hh;
    }
    row[15] = 0u;
    #pragma unroll
    for (int sel = 0; sel < 3; sel++) {
        int uo = (sel == 2) ? 16 : (32 + 10 * sel);
        #pragma unroll
        for (int op = 0; op < D / 2; op++) {
            __half2 accA = __floats2half2_rn(0.f, 0.f);
            __half2 accB = __floats2half2_rn(0.f, 0.f);
            #pragma unroll
            for (int jj = 0; jj < 10; jj++) {
                accA = __hfma2(h2[jj], *(const __half2*)&s_W2[sel * 200 + (2 * op) * 10 + jj], accA);
                accB = __hfma2(h2[jj], *(const __half2*)&s_W2[sel * 200 + (2 * op + 1) * 10 + jj], accB);
            }
            float2 fa = __half22float2(accA);
            float2 fb = __half22float2(accB);
            __half2 hh = __floats2half2_rn(fa.x + fa.y, fb.x + fb.y);
            row[uo + op] = *(unsigned*)&hh;
        }
    }
    __syncthreads();

    // coalesced store, skipping never-read pad uints (26..31, 52..63)
    for (int f = tid; f < nblk * NHW; f += 256) {
        int nn = f >> 6, u = f & 63;
        if (u < 26 || (u >= 32 && u < 52))
            g_NH[(size_t)(base + nn) * NHW + u] = s_row[nn * 65 + u];
    }
}

// ---------------- layer 0: h == 0, 8 lanes per edge, 16-iter loop (64 edges/warp) ---
__global__ __launch_bounds__(256) void k_edge0(
    const int* __restrict__ rel, const int* __restrict__ qrel,
    const int* __restrict__ rtime, const int* __restrict__ dst,
    float* __restrict__ hout, int E)
{
    int tid = threadIdx.x, lane = tid & 31, wid = tid >> 5;
    int grp = lane >> 3, sub = lane & 7;
    int base = (blockIdx.x * 8 + wid) * EPW;
    #pragma unroll
    for (int it = 0; it < EPW / 4; it++) {
        int ew = base + it * 4 + grp;
        bool valid = ew < E;
        int ei = valid ? ew : 0;
        int dn = dst[ei], r = rel[ei], q = qrel[ei], rt = rtime[ei];
        int sel = (rt > 0) ? 2 : ((rt == 0) ? 1 : 0);
        int ta = rt < 0 ? -rt : rt;
        float score = g_S0[r * NRELP1 + q];
        if (valid && sub < 5) {
            float4 rw = *(const float4*)(g_RWp + (sel * NRELP1 + r) * DP + sub * 4);
            float4 tw = *(const float4*)(g_TWp + (sel * NTIME + ta) * DP + sub * 4);
            red_add_v4(hout + (size_t)dn * D + sub * 4,
                       score * (rw.x + tw.x), score * (rw.y + tw.y),
                       score * (rw.z + tw.z), score * (rw.w + tw.w));
        }
    }
}

// ---------------- generic layer: 8 lanes/edge, fp16 node row, 16-iter loop ----------
__global__ __launch_bounds__(256) void k_edge(
    const int* __restrict__ src, const int* __restrict__ dst,
    const int* __restrict__ rel, const int* __restrict__ qrel,
    const int* __restrict__ rtime, const float* __restrict__ w2,
    float* __restrict__ hout, int E)
{
    int tid = threadIdx.x, lane = tid & 31, wid = tid >> 5;
    int grp = lane >> 3, sub = lane & 7;
    float w2r0 = (sub * 4 + 0 < K1) ? w2[sub * 4 + 0] : 0.f;
    float w2r1 = (sub * 4 + 1 < K1) ? w2[sub * 4 + 1] : 0.f;
    float w2r2 = (sub * 4 + 2 < K1) ? w2[sub * 4 + 2] : 0.f;
    float w2r3 = (sub * 4 + 3 < K1) ? w2[sub * 4 + 3] : 0.f;
    int base = (blockIdx.x * 8 + wid) * EPW;
    #pragma unroll
    for (int it = 0; it < EPW / 4; it++) {
        int ew = base + it * 4 + grp;
        bool valid = ew < E;
        int ei = valid ? ew : 0;
        int sn = src[ei], dn = dst[ei], r = rel[ei], q = qrel[ei], rt = rtime[ei];
        int sel = (rt > 0) ? 2 : ((rt == 0) ? 1 : 0);
        int ta = rt < 0 ? -rt : rt;
        const unsigned* nrow = g_NH + (size_t)sn * NHW;
        // attention: 8 lanes cover 32 halves of HA
        uint2 hv = *(const uint2*)(nrow + sub * 2);
        float2 f01 = __half22float2(*(const __half2*)&hv.x);
        float2 f23 = __half22float2(*(const __half2*)&hv.y);
        float4 pb = *(const float4*)(g_PBC + (size_t)(r * NRELP1 + q) * DP + sub * 4);
        float p = fmaxf(f01.x + pb.x, 0.f) * w2r0;
        p = fmaf(fmaxf(f01.y + pb.y, 0.f), w2r1, p);
        p = fmaf(fmaxf(f23.x + pb.z, 0.f), w2r2, p);
        p = fmaf(fmaxf(f23.y + pb.w, 0.f), w2r3, p);
        p += __shfl_xor_sync(0xffffffffu, p, 1);
        p += __shfl_xor_sync(0xffffffffu, p, 2);
        p += __shfl_xor_sync(0xffffffffu, p, 4);
        float score = 1.f / (1.f + __expf(-p));
        // message: lanes 0..4 cover 20 floats
        if (valid && sub < 5) {
            int uo = (sel == 2) ? 16 : (32 + 10 * sel);
            uint2 tv = *(const uint2*)(nrow + uo + sub * 2);
            float2 t01 = __half22float2(*(const __half2*)&tv.x);
            float2 t23 = __half22float2(*(const __half2*)&tv.y);
            float4 rw = *(const float4*)(g_RWp + (sel * NRELP1 + r) * DP + sub * 4);
            float4 tw = *(const float4*)(g_TWp + (sel * NTIME + ta) * DP + sub * 4);
            red_add_v4(hout + (size_t)dn * D + sub * 4,
                       score * (t01.x + rw.x + tw.x), score * (t01.y + rw.y + tw.y),
                       score * (t23.x + rw.z + tw.z), score * (t23.y + rw.w + tw.w));
        }
    }
}

// ---------------- final: leaky -> dot(w_cls) + b -> scatter ----------------
__global__ __launch_bounds__(256) void k_final(
    const float* __restrict__ hin, const int* __restrict__ nb,
    const int* __restrict__ ne, const float* __restrict__ wcls,
    const float* __restrict__ bcls, const int* __restrict__ pne,
    float* __restrict__ out, int n)
{
    int i = blockIdx.x * blockDim.x + threadIdx.x;
    if (i >= n) return;
    const float4* hp = (const float4*)(hin + (size_t)i * D);
    float acc = bcls[0];
    #pragma unroll
    for (int g = 0; g < D / 4; g++) {
        float4 v = hp[g];
        acc = fmaf(leaky(v.x), __ldg(wcls + 4 * g + 0), acc);
        acc = fmaf(leaky(v.y), __ldg(wcls + 4 * g + 1), acc);
        acc = fmaf(leaky(v.z), __ldg(wcls + 4 * g + 2), acc);
        acc = fmaf(leaky(v.w), __ldg(wcls + 4 * g + 3), acc);
    }
    long long idx = (long long)nb[i] * (long long)pne[0] + (long long)ne[i];
    out[idx] = acc;
}

// ---------------- host ----------------
extern "C" void kernel_launch(void* const* d_in, const int* in_sizes, int n_in,
                              void* d_out, int out_size)
{
    const int*   src   = (const int*)d_in[0];
    const int*   dst   = (const int*)d_in[1];
    const int*   rel   = (const int*)d_in[2];
    const int*   qrel  = (const int*)d_in[3];
    const int*   rtime = (const int*)d_in[4];
    const int*   nb    = (const int*)d_in[5];
    const int*   ne    = (const int*)d_in[6];
    const float* rela  = (const float*)d_in[7];
    const float* tem   = (const float*)d_in[8];
    const float* w1    = (const float*)d_in[9];
    const float* w2    = (const float*)d_in[10];
    const float* wp    = (const float*)d_in[11];
    const float* wn    = (const float*)d_in[12];
    const float* wf    = (const float*)d_in[13];
    const float* wcls  = (const float*)d_in[14];
    const float* bcls  = (const float*)d_in[15];
    const int*   pne   = (const int*)d_in[17];

    int E  = in_sizes[0] / NLAYERS;
    int Nn = in_sizes[5];

    float *b0, *b1;
    cudaGetSymbolAddress((void**)&b0, g_buf0);
    cudaGetSymbolAddress((void**)&b1, g_buf1);
    size_t bufBytes = (size_t)Nn * D * sizeof(float);

    const int SMEM_NODE = 900 * 4 + 256 * 21 * 4 + 256 * 65 * 4;  // ~92 KB
    static int smem_set = 0;
    if (!smem_set) {
        cudaFuncSetAttribute(k_node, cudaFuncAttributeMaxDynamicSharedMemorySize, SMEM_NODE);
        smem_set = 1;
    }

    // small tables
    const int NTAB = 2 * NRELP1 * DP + 3 * NRELP1 * DP + 3 * NTIME * DP;
    k_tables<<<(NTAB + 255) / 256, 256>>>(rela, tem, w1, wp, wn, wf);
    k_s0<<<(NRELP1 * NRELP1 + 255) / 256, 256>>>(w2);
    k_pbc<<<(NRELP1 * NRELP1 * DP + 255) / 256, 256>>>();

    int gE = (E + 8 * EPW - 1) / (8 * EPW);   // 512 edges per block (8 warps x 64 edges)
    int gN = (Nn + 255) / 256;

    // layer 0 (h = 0): accumulate into buf1
    cudaMemsetAsync(b1, 0, bufBytes);
    k_edge0<<<gE, 256>>>(rel, qrel, rtime, dst, b1, E);

    // layer 1: node precompute from buf1, edges -> buf0
    k_node<<<gN, 256, SMEM_NODE>>>(b1, w1, wp, wn, wf, Nn);
    cudaMemsetAsync(b0, 0, bufBytes);
    k_edge<<<gE, 256>>>(src + E, dst + E, rel + E, qrel + E, rtime + E, w2, b0, E);

    // layer 2: node precompute from buf0, edges -> buf1
    k_node<<<gN, 256, SMEM_NODE>>>(b0, w1, wp, wn, wf, Nn);
    cudaMemsetAsync(b1, 0, bufBytes);
    k_edge<<<gE, 256>>>(src + 2 * E, dst + 2 * E, rel + 2 * E, qrel + 2 * E, rtime + 2 * E,
                        w2, b1, E);

    // output: zero then scatter
    cudaMemsetAsync(d_out, 0, (size_t)out_size * sizeof(float));
    k_final<<<(Nn + 255) / 256, 256>>>(b1, nb, ne, wcls, bcls, pne, (float*)d_out, Nn);
}

// round 17
// speedup vs baseline: 1.2320x; 1.1680x over previous
#include <cuda_runtime.h>
#include <cuda_fp16.h>
#include <math.h>

#define D       20
#define K1      30
#define DP      32          // table row stride (128B)
#define HR      12          // uints per fp16 hidden row (48B, 16B-aligned)
#define NRELP1  201
#define NTIME   365
#define NLAYERS 3
#define MAXN    1000000
#define NHW     64          // uints per node row in g_NH (256B)

// ---------------- scratch (device globals; no runtime allocation) ----------------
__device__ __align__(16) unsigned g_bufh0[MAXN * HR];             // 48 MB fp16 hidden
__device__ __align__(16) unsigned g_bufh1[MAXN * HR];             // 48 MB fp16 hidden
__device__ __align__(16) float    g_PbP[NRELP1 * DP];
__device__ __align__(16) float    g_PcP[NRELP1 * DP];
__device__ __align__(16) float    g_PBC[NRELP1 * NRELP1 * DP];    // Pb[r]+Pc[q], 5.2 MB
__device__ __align__(16) float    g_RWp[3 * NRELP1 * DP];
__device__ __align__(16) float    g_TWp[3 * NTIME * DP];
__device__ __align__(16) float    g_S0[NRELP1 * NRELP1];
// packed fp16 node row: HA uints 0..14 (pad 15), HT2 uints 16..25,
// HT0 uints 32..41, HT1 uints 42..51; pads never read.
__device__ __align__(16) unsigned g_NH[(size_t)MAXN * NHW];       // 256 MB

// fp16x2 vector reductions (sm_90+)
__device__ __forceinline__ void red_add_h8(unsigned* addr, unsigned a, unsigned b,
                                           unsigned c, unsigned d) {
    asm volatile(
        "{ .reg .u64 p; cvta.to.global.u64 p, %0;\n\t"
        "  red.global.add.noftz.v4.f16x2 [p], {%1, %2, %3, %4}; }\n\t"
        :: "l"(addr), "r"(a), "r"(b), "r"(c), "r"(d) : "memory");
}
__device__ __forceinline__ void red_add_h4(unsigned* addr, unsigned a, unsigned b) {
    asm volatile(
        "{ .reg .u64 p; cvta.to.global.u64 p, %0;\n\t"
        "  red.global.add.noftz.v2.f16x2 [p], {%1, %2}; }\n\t"
        :: "l"(addr), "r"(a), "r"(b) : "memory");
}

__device__ __forceinline__ float leaky(float x) { return x > 0.f ? x : 0.01f * x; }

// pack 4 floats scaled by s into 2 f16x2 uints
__device__ __forceinline__ void pack2(float s, float m0, float m1, float m2, float m3,
                                      unsigned& u0, unsigned& u1) {
    __half2 a = __floats2half2_rn(s * m0, s * m1);
    __half2 b = __floats2half2_rn(s * m2, s * m3);
    u0 = *(unsigned*)&a;
    u1 = *(unsigned*)&b;
}

// ---------------- small-table precompute ----------------
__global__ void k_tables(const float* __restrict__ rela, const float* __restrict__ tem,
                         const float* __restrict__ w1,
                         const float* __restrict__ wp, const float* __restrict__ wn,
                         const float* __restrict__ wf)
{
    int i = blockIdx.x * blockDim.x + threadIdx.x;
    const int NPB  = NRELP1 * DP;
    const int NRW  = 3 * NRELP1 * DP;
    const int NTW  = 3 * NTIME * DP;
    if (i < NPB) {
        int r = i / DP, k = i % DP;
        float a = 0.f;
        if (k < K1) {
            #pragma unroll
            for (int j = 0; j < D; j++) a = fmaf(rela[r * D + j], w1[k * (3 * D) + D + j], a);
        }
        g_PbP[i] = a;
    } else if (i < 2 * NPB) {
        int t = i - NPB;
        int r = t / DP, k = t % DP;
        float a = 0.f;
        if (k < K1) {
            #pragma unroll
            for (int j = 0; j < D; j++) a = fmaf(rela[r * D + j], w1[k * (3 * D) + 2 * D + j], a);
        }
        g_PcP[t] = a;
    } else if (i < 2 * NPB + NRW) {
        int t = i - 2 * NPB;
        int s = t / (NRELP1 * DP);
        int rem = t % (NRELP1 * DP);
        int r = rem / DP, o = rem % DP;
        float a = 0.f;
        if (o < D) {
            const float* W = (s == 0) ? wp : ((s == 1) ? wn : wf);
            #pragma unroll
            for (int j = 0; j < D; j++) a = fmaf(rela[r * D + j], W[o * D + j], a);
        }
        g_RWp[t] = a;
    } else if (i < 2 * NPB + NRW + NTW) {
        int t = i - 2 * NPB - NRW;
        int s = t / (NTIME * DP);
        int rem = t % (NTIME * DP);
        int tt = rem / DP, o = rem % DP;
        float a = 0.f;
        if (o < D) {
            const float* W = (s == 0) ? wp : ((s == 1) ? wn : wf);
            #pragma unroll
            for (int j = 0; j < D; j++) a = fmaf(tem[tt * D + j], W[o * D + j], a);
        }
        g_TWp[t] = a;
    }
}

// PBC[r][q][k] = PbP[r][k] + PcP[q][k]
__global__ void k_pbc()
{
    int i = blockIdx.x * blockDim.x + threadIdx.x;
    if (i >= NRELP1 * NRELP1 * DP) return;
    int k = i & (DP - 1);
    int rq = i >> 5;
    int q = rq % NRELP1, r = rq / NRELP1;
    g_PBC[i] = g_PbP[r * DP + k] + g_PcP[q * DP + k];
}

// layer-0 score table
__global__ void k_s0(const float* __restrict__ w2)
{
    int i = blockIdx.x * blockDim.x + threadIdx.x;
    if (i >= NRELP1 * NRELP1) return;
    int r = i / NRELP1, q = i % NRELP1;
    float s = 0.f;
    #pragma unroll
    for (int k = 0; k < K1; k++) {
        float a = g_PbP[r * DP + k] + g_PcP[q * DP + k];
        a = fmaxf(a, 0.f);
        s = fmaf(a, w2[k], s);
    }
    g_S0[i] = 1.f / (1.f + __expf(-s));
}

// ---------------- node precompute (half2 math) from fp16 hidden rows ----------------
__global__ __launch_bounds__(256) void k_node(
    const unsigned* __restrict__ hin,
    const float* __restrict__ w1, const float* __restrict__ wp,
    const float* __restrict__ wn, const float* __restrict__ wf, int Nn)
{
    extern __shared__ float sm[];
    unsigned* s_w1a2 = (unsigned*)sm;                 // [K1*10]  w1a rows, half2-packed
    unsigned* s_W2   = (unsigned*)sm + 300;           // [3*D*10] W rows, half2-packed
    unsigned* s_hu   = (unsigned*)sm + 900;           // [256*13] fp16 row staging
    unsigned* s_row  = (unsigned*)sm + 900 + 256 * 13;   // [256*65]

    int tid = threadIdx.x;
    for (int i = tid; i < K1 * 10; i += 256) {
        int o = i / 10, jj = i % 10;
        __half2 hh = __floats2half2_rn(w1[o * (3 * D) + 2 * jj], w1[o * (3 * D) + 2 * jj + 1]);
        s_w1a2[i] = *(unsigned*)&hh;
    }
    for (int i = tid; i < 3 * D * 10; i += 256) {
        int s = i / (D * 10); int rm = i % (D * 10);
        int o = rm / 10, jj = rm % 10;
        const float* W = (s == 0) ? wp : ((s == 1) ? wn : wf);
        __half2 hh = __floats2half2_rn(W[o * D + 2 * jj], W[o * D + 2 * jj + 1]);
        s_W2[i] = *(unsigned*)&hh;
    }
    int base = blockIdx.x * 256;
    int nblk = Nn - base; if (nblk > 256) nblk = 256;

    // stage fp16 hidden rows coalesced
    for (int f = tid; f < nblk * HR; f += 256)
        s_hu[(f / HR) * 13 + (f % HR)] = hin[(size_t)base * HR + f];
    __syncthreads();

    // unpack own row, apply leaky, repack to half2
    __half2 h2[10];
    #pragma unroll
    for (int jj = 0; jj < 10; jj++) {
        unsigned u = s_hu[tid * 13 + jj];
        float2 f2 = __half22float2(*(const __half2*)&u);
        h2[jj] = __floats2half2_rn(leaky(f2.x), leaky(f2.y));
    }

    unsigned* row = s_row + tid * 65;
    #pragma unroll
    for (int op = 0; op < K1 / 2; op++) {
        __half2 accA = __floats2half2_rn(0.f, 0.f);
        __half2 accB = __floats2half2_rn(0.f, 0.f);
        #pragma unroll
        for (int jj = 0; jj < 10; jj++) {
            accA = __hfma2(h2[jj], *(const __half2*)&s_w1a2[(2 * op) * 10 + jj], accA);
            accB = __hfma2(h2[jj], *(const __half2*)&s_w1a2[(2 * op + 1) * 10 + jj], accB);
        }
        float2 fa = __half22float2(accA);
        float2 fb = __half22float2(accB);
        __half2 hh = __floats2half2_rn(fa.x + fa.y, fb.x + fb.y);
        row[op] = *(unsigned*)&hh;
    }
    row[15] = 0u;
    #pragma unroll
    for (int sel = 0; sel < 3; sel++) {
        int uo = (sel == 2) ? 16 : (32 + 10 * sel);
        #pragma unroll
        for (int op = 0; op < D / 2; op++) {
            __half2 accA = __floats2half2_rn(0.f, 0.f);
            __half2 accB = __floats2half2_rn(0.f, 0.f);
            #pragma unroll
            for (int jj = 0; jj < 10; jj++) {
                accA = __hfma2(h2[jj], *(const __half2*)&s_W2[sel * 200 + (2 * op) * 10 + jj], accA);
                accB = __hfma2(h2[jj], *(const __half2*)&s_W2[sel * 200 + (2 * op + 1) * 10 + jj], accB);
            }
            float2 fa = __half22float2(accA);
            float2 fb = __half22float2(accB);
            __half2 hh = __floats2half2_rn(fa.x + fa.y, fb.x + fb.y);
            row[uo + op] = *(unsigned*)&hh;
        }
    }
    __syncthreads();

    // coalesced store, skipping never-read pad uints (26..31, 52..63)
    for (int f = tid; f < nblk * NHW; f += 256) {
        int nn = f >> 6, u = f & 63;
        if (u < 26 || (u >= 32 && u < 52))
            g_NH[(size_t)(base + nn) * NHW + u] = s_row[nn * 65 + u];
    }
}

// scatter helper: lanes 0..4 hold (u0,u1); funnel 1->0, 3->2; 3 red ops per edge
__device__ __forceinline__ void scatter_h(unsigned* rowp, int grp, int sub, bool valid,
                                          unsigned u0, unsigned u1) {
    unsigned w0 = __shfl_sync(0xffffffffu, u0, grp * 8 + sub + 1);
    unsigned w1 = __shfl_sync(0xffffffffu, u1, grp * 8 + sub + 1);
    if (valid) {
        if (sub == 0)      red_add_h8(rowp + 0, u0, u1, w0, w1);
        else if (sub == 2) red_add_h8(rowp + 4, u0, u1, w0, w1);
        else if (sub == 4) red_add_h4(rowp + 8, u0, u1);
    }
}

// ---------------- layer 0: h == 0, 8 lanes per edge, 8-iter loop --------------------
__global__ __launch_bounds__(256) void k_edge0(
    const int* __restrict__ rel, const int* __restrict__ qrel,
    const int* __restrict__ rtime, const int* __restrict__ dst,
    unsigned* __restrict__ hout, int E)
{
    int tid = threadIdx.x, lane = tid & 31, wid = tid >> 5;
    int grp = lane >> 3, sub = lane & 7;
    int base = (blockIdx.x * 8 + wid) * 32;
    #pragma unroll
    for (int it = 0; it < 8; it++) {
        int ew = base + it * 4 + grp;
        bool valid = ew < E;
        int ei = valid ? ew : 0;
        int dn = dst[ei], r = rel[ei], q = qrel[ei], rt = rtime[ei];
        int sel = (rt > 0) ? 2 : ((rt == 0) ? 1 : 0);
        int ta = rt < 0 ? -rt : rt;
        float score = g_S0[r * NRELP1 + q];
        unsigned u0 = 0u, u1 = 0u;
        if (sub < 5) {
            float4 rw = *(const float4*)(g_RWp + (sel * NRELP1 + r) * DP + sub * 4);
            float4 tw = *(const float4*)(g_TWp + (sel * NTIME + ta) * DP + sub * 4);
            pack2(score, rw.x + tw.x, rw.y + tw.y, rw.z + tw.z, rw.w + tw.w, u0, u1);
        }
        scatter_h(hout + (size_t)dn * HR, grp, sub, valid, u0, u1);
    }
}

// ---------------- generic layer: 8 lanes per edge, fp16 node row, 8-iter loop -------
__global__ __launch_bounds__(256) void k_edge(
    const int* __restrict__ src, const int* __restrict__ dst,
    const int* __restrict__ rel, const int* __restrict__ qrel,
    const int* __restrict__ rtime, const float* __restrict__ w2,
    unsigned* __restrict__ hout, int E)
{
    int tid = threadIdx.x, lane = tid & 31, wid = tid >> 5;
    int grp = lane >> 3, sub = lane & 7;
    float w2r0 = (sub * 4 + 0 < K1) ? w2[sub * 4 + 0] : 0.f;
    float w2r1 = (sub * 4 + 1 < K1) ? w2[sub * 4 + 1] : 0.f;
    float w2r2 = (sub * 4 + 2 < K1) ? w2[sub * 4 + 2] : 0.f;
    float w2r3 = (sub * 4 + 3 < K1) ? w2[sub * 4 + 3] : 0.f;
    int base = (blockIdx.x * 8 + wid) * 32;
    #pragma unroll
    for (int it = 0; it < 8; it++) {
        int ew = base + it * 4 + grp;
        bool valid = ew < E;
        int ei = valid ? ew : 0;
        int sn = src[ei], dn = dst[ei], r = rel[ei], q = qrel[ei], rt = rtime[ei];
        int sel = (rt > 0) ? 2 : ((rt == 0) ? 1 : 0);
        int ta = rt < 0 ? -rt : rt;
        const unsigned* nrow = g_NH + (size_t)sn * NHW;
        // attention: 8 lanes cover 32 halves of HA
        uint2 hv = *(const uint2*)(nrow + sub * 2);
        float2 f01 = __half22float2(*(const __half2*)&hv.x);
        float2 f23 = __half22float2(*(const __half2*)&hv.y);
        float4 pb = *(const float4*)(g_PBC + (size_t)(r * NRELP1 + q) * DP + sub * 4);
        float p = fmaxf(f01.x + pb.x, 0.f) * w2r0;
        p = fmaf(fmaxf(f01.y + pb.y, 0.f), w2r1, p);
        p = fmaf(fmaxf(f23.x + pb.z, 0.f), w2r2, p);
        p = fmaf(fmaxf(f23.y + pb.w, 0.f), w2r3, p);
        p += __shfl_xor_sync(0xffffffffu, p, 1);
        p += __shfl_xor_sync(0xffffffffu, p, 2);
        p += __shfl_xor_sync(0xffffffffu, p, 4);
        float score = 1.f / (1.f + __expf(-p));
        // message: lanes 0..4 compute 4 floats each, pack to f16x2
        unsigned u0 = 0u, u1 = 0u;
        if (sub < 5) {
            int uo = (sel == 2) ? 16 : (32 + 10 * sel);
            uint2 tv = *(const uint2*)(nrow + uo + sub * 2);
            float2 t01 = __half22float2(*(const __half2*)&tv.x);
            float2 t23 = __half22float2(*(const __half2*)&tv.y);
            float4 rw = *(const float4*)(g_RWp + (sel * NRELP1 + r) * DP + sub * 4);
            float4 tw = *(const float4*)(g_TWp + (sel * NTIME + ta) * DP + sub * 4);
            pack2(score, t01.x + rw.x + tw.x, t01.y + rw.y + tw.y,
                  t23.x + rw.z + tw.z, t23.y + rw.w + tw.w, u0, u1);
        }
        scatter_h(hout + (size_t)dn * HR, grp, sub, valid, u0, u1);
    }
}

// ---------------- final: leaky -> dot(w_cls) + b -> scatter ----------------
__global__ __launch_bounds__(256) void k_final(
    const unsigned* __restrict__ hin, const int* __restrict__ nb,
    const int* __restrict__ ne, const float* __restrict__ wcls,
    const float* __restrict__ bcls, const int* __restrict__ pne,
    float* __restrict__ out, int n)
{
    int i = blockIdx.x * blockDim.x + threadIdx.x;
    if (i >= n) return;
    const unsigned* rp = hin + (size_t)i * HR;
    float acc = bcls[0];
    #pragma unroll
    for (int jj = 0; jj < 10; jj++) {
        unsigned u = rp[jj];
        float2 f2 = __half22float2(*(const __half2*)&u);
        acc = fmaf(leaky(f2.x), __ldg(wcls + 2 * jj + 0), acc);
        acc = fmaf(leaky(f2.y), __ldg(wcls + 2 * jj + 1), acc);
    }
    long long idx = (long long)nb[i] * (long long)pne[0] + (long long)ne[i];
    out[idx] = acc;
}

// ---------------- host ----------------
extern "C" void kernel_launch(void* const* d_in, const int* in_sizes, int n_in,
                              void* d_out, int out_size)
{
    const int*   src   = (const int*)d_in[0];
    const int*   dst   = (const int*)d_in[1];
    const int*   rel   = (const int*)d_in[2];
    const int*   qrel  = (const int*)d_in[3];
    const int*   rtime = (const int*)d_in[4];
    const int*   nb    = (const int*)d_in[5];
    const int*   ne    = (const int*)d_in[6];
    const float* rela  = (const float*)d_in[7];
    const float* tem   = (const float*)d_in[8];
    const float* w1    = (const float*)d_in[9];
    const float* w2    = (const float*)d_in[10];
    const float* wp    = (const float*)d_in[11];
    const float* wn    = (const float*)d_in[12];
    const float* wf    = (const float*)d_in[13];
    const float* wcls  = (const float*)d_in[14];
    const float* bcls  = (const float*)d_in[15];
    const int*   pne   = (const int*)d_in[17];

    int E  = in_sizes[0] / NLAYERS;
    int Nn = in_sizes[5];

    unsigned *b0, *b1;
    cudaGetSymbolAddress((void**)&b0, g_bufh0);
    cudaGetSymbolAddress((void**)&b1, g_bufh1);
    size_t bufBytes = (size_t)Nn * HR * sizeof(unsigned);

    const int SMEM_NODE = 900 * 4 + 256 * 13 * 4 + 256 * 65 * 4;  // ~84 KB
    static int smem_set = 0;
    if (!smem_set) {
        cudaFuncSetAttribute(k_node, cudaFuncAttributeMaxDynamicSharedMemorySize, SMEM_NODE);
        smem_set = 1;
    }

    // small tables
    const int NTAB = 2 * NRELP1 * DP + 3 * NRELP1 * DP + 3 * NTIME * DP;
    k_tables<<<(NTAB + 255) / 256, 256>>>(rela, tem, w1, wp, wn, wf);
    k_s0<<<(NRELP1 * NRELP1 + 255) / 256, 256>>>(w2);
    k_pbc<<<(NRELP1 * NRELP1 * DP + 255) / 256, 256>>>();

    int gE = (E + 255) / 256;        // 256 edges per block (8 warps x 32 edges)
    int gN = (Nn + 255) / 256;

    // layer 0 (h = 0): accumulate into buf1
    cudaMemsetAsync(b1, 0, bufBytes);
    k_edge0<<<gE, 256>>>(rel, qrel, rtime, dst, b1, E);

    // layer 1: node precompute from buf1, edges -> buf0
    k_node<<<gN, 256, SMEM_NODE>>>(b1, w1, wp, wn, wf, Nn);
    cudaMemsetAsync(b0, 0, bufBytes);
    k_edge<<<gE, 256>>>(src + E, dst + E, rel + E, qrel + E, rtime + E, w2, b0, E);

    // layer 2: node precompute from buf0, edges -> buf1
    k_node<<<gN, 256, SMEM_NODE>>>(b0, w1, wp, wn, wf, Nn);
    cudaMemsetAsync(b1, 0, bufBytes);
    k_edge<<<gE, 256>>>(src + 2 * E, dst + 2 * E, rel + 2 * E, qrel + 2 * E, rtime + 2 * E,
                        w2, b1, E);

    // output: zero then scatter
    cudaMemsetAsync(d_out, 0, (size_t)out_size * sizeof(float));
    k_final<<<(Nn + 255) / 256, 256>>>(b1, nb, ne, wcls, bcls, pne, (float*)d_out, Nn);
}